// round 15
// baseline (speedup 1.0000x reference)
#include <cuda_runtime.h>
#include <cuda_bf16.h>
#include <cstdint>

// Problem constants: B=4, S=2048, D=1024, U=1024, fp32 in/out.
#define BB 4
#define SSQ 2048
#define DD 1024
#define UU 1024

// ---------------------------------------------------------------------------
// Global scratch (device globals, allocation-free per harness rules).
// K-extended bf16 hi/lo splits: A-side [hi|lo|hi], B-side [hi|hi|lo] along K,
// so one plain bf16 GEMM over 3K computes Ahi*Bhi + Alo*Bhi + Ahi*Blo
// (dropped lo*lo term ~2^-18 relative).
// ---------------------------------------------------------------------------
__device__ __align__(16) __nv_bfloat16 g_xe[(size_t)8192 * 3072];      // X ext (A)
__device__ __align__(16) __nv_bfloat16 g_we[(size_t)3 * 1024 * 3072];  // W^T ext (B) x3
__device__ __align__(16) __nv_bfloat16 g_qe[(size_t)BB * 2048 * 3072]; // Q ext (A)
__device__ __align__(16) __nv_bfloat16 g_ke[(size_t)BB * 2048 * 3072]; // K ext (B, NT)
__device__ __align__(16) __nv_bfloat16 g_ve[(size_t)BB * 6144 * 1024]; // V ext (B, NN rows)
__device__ __align__(16) float         g_s[(size_t)BB * SSQ * SSQ];    // scores
__device__ __align__(16) __nv_bfloat16 g_pe[(size_t)BB * 2048 * 6144]; // P ext (A)

// ---------------------------------------------------------------------------
// Baseline-ISA helpers (sm_80 cp.async / ldmatrix / mma.sync only — nothing
// 'a'-gated; harness compiles for plain sm_103).
// ---------------------------------------------------------------------------
__device__ __forceinline__ uint32_t smem_u32(const void* p) {
    return (uint32_t)__cvta_generic_to_shared(p);
}
__device__ __forceinline__ void cp16(uint32_t s, const void* g) {
    asm volatile("cp.async.cg.shared.global [%0], [%1], 16;"
                 :: "r"(s), "l"(__cvta_generic_to_global(g)) : "memory");
}
#define CP_COMMIT() asm volatile("cp.async.commit_group;" ::: "memory")
#define CP_WAIT1()  asm volatile("cp.async.wait_group 1;" ::: "memory")
#define CP_WAIT0()  asm volatile("cp.async.wait_group 0;" ::: "memory")

__device__ __forceinline__ void ldsm4(uint32_t* r, uint32_t addr) {
    asm volatile("ldmatrix.sync.aligned.m8n8.x4.shared.b16 {%0,%1,%2,%3}, [%4];"
                 : "=r"(r[0]), "=r"(r[1]), "=r"(r[2]), "=r"(r[3]) : "r"(addr));
}
__device__ __forceinline__ void ldsm4t(uint32_t* r, uint32_t addr) {
    asm volatile("ldmatrix.sync.aligned.m8n8.x4.trans.shared.b16 {%0,%1,%2,%3}, [%4];"
                 : "=r"(r[0]), "=r"(r[1]), "=r"(r[2]), "=r"(r[3]) : "r"(addr));
}
__device__ __forceinline__ void mma16816(float* c, const uint32_t* a,
                                         const uint32_t* b) {
    asm volatile(
        "mma.sync.aligned.m16n8k16.row.col.f32.bf16.bf16.f32 "
        "{%0,%1,%2,%3}, {%4,%5,%6,%7}, {%8,%9}, {%0,%1,%2,%3};"
        : "+f"(c[0]), "+f"(c[1]), "+f"(c[2]), "+f"(c[3])
        : "r"(a[0]), "r"(a[1]), "r"(a[2]), "r"(a[3]), "r"(b[0]), "r"(b[1]));
}

// hi/lo bf16 split of an fp32 pair, packed as two b16x2 words.
__device__ __forceinline__ void split2(float f0, float f1,
                                       uint32_t& hip, uint32_t& lop) {
    __nv_bfloat16 h0 = __float2bfloat16_rn(f0);
    __nv_bfloat16 h1 = __float2bfloat16_rn(f1);
    __nv_bfloat16 l0 = __float2bfloat16_rn(f0 - __bfloat162float(h0));
    __nv_bfloat16 l1 = __float2bfloat16_rn(f1 - __bfloat162float(h1));
    hip = (uint32_t)*(uint16_t*)&h0 | ((uint32_t)*(uint16_t*)&h1 << 16);
    lop = (uint32_t)*(uint16_t*)&l0 | ((uint32_t)*(uint16_t*)&l1 << 16);
}

// K-chunk = 64, triple-buffered. A/B NT tiles: 128 rows x 64 halves padded to
// 72 (144B stride: odd 16B multiple -> conflict-free ldmatrix).
#define KCH 64
#define ASTR 72
#define ATILEB (128 * ASTR * 2)              // 18432 B per buffer
#define NT_SMEM (6 * ATILEB)                 // 3 stages x (A+B) = 110592 B
#define BSTRNN 136                           // NN B row: 128 + 8 pad halves
#define BTILEB_NN (64 * BSTRNN * 2)          // 17408 B per buffer
#define NN_SMEM (3 * ATILEB + 3 * BTILEB_NN) // 107520 B

#define NUM_PERS 304                         // persistent CTAs (2/SM)

// ---------------------------------------------------------------------------
// NT GEMM: C[M,N] = A[M,Ke] @ B[N,Ke]^T, bf16 K-major both sides.
// Persistent CTAs grid-stride over 128x128 tiles. 8 warps (2m x 4n), warp
// tile 64x32 of m16n8k16 HMMA. 3-stage cp.async pipeline, ONE sync per
// chunk: wait g(t) -> sync (proves chunk t visible AND buf (t+2)%3 free,
// since its last reader compute(t-1) finished before any warp reached this
// barrier) -> stage(t+2) -> compute(t).
// QKV=true: epilogue writes ext bf16 per z (z=0 qe, z=1 ke, z=2 ve).
// ---------------------------------------------------------------------------
template <bool QKV>
__global__ __launch_bounds__(256, 2)
void gemm_nt(const __nv_bfloat16* __restrict__ Ag,
             const __nv_bfloat16* __restrict__ Bg,
             float* __restrict__ Cf,
             __nv_bfloat16* __restrict__ dq,
             __nv_bfloat16* __restrict__ dk,
             __nv_bfloat16* __restrict__ dv,
             int N, long long Ke, long long sA, long long sB, long long sC,
             int ntx, int nty, int ntotal)
{
    extern __shared__ __align__(16) char dsm[];
    const uint32_t base = smem_u32(dsm);
    uint32_t sa[3], sb[3];
    #pragma unroll
    for (int i = 0; i < 3; ++i) {
        sa[i] = base + i * ATILEB;
        sb[i] = base + (3 + i) * ATILEB;
    }

    const int tid  = threadIdx.x;
    const int lane = tid & 31;
    const int wid  = tid >> 5;
    const int m0w  = (wid >> 2) * 64;
    const int n0w  = (wid & 3) * 32;

    const int arow = lane & 15;
    const int akh  = (lane >> 4) * 8;
    const int brow = (lane & 7) + ((lane >> 4) << 3);
    const int bkh  = ((lane >> 3) & 1) * 8;
    const int rr   = lane >> 2;
    const int cc2  = (lane & 3) * 2;

    const int nch = (int)(Ke / KCH);

    for (int tile = blockIdx.x; tile < ntotal; tile += gridDim.x) {
        const int bx = tile % ntx;
        const int t2 = tile / ntx;
        const int by = t2 % nty;
        const int bz = t2 / nty;

        const __nv_bfloat16* A =
            Ag + (long long)bz * sA + (size_t)by * 128 * Ke;
        const __nv_bfloat16* B =
            Bg + (long long)bz * sB + (size_t)bx * 128 * Ke;

        auto stage = [&](int ck, int b) {
            const size_t kof = (size_t)ck * KCH;
            #pragma unroll
            for (int i = 0; i < 4; ++i) {
                const int id  = tid + i * 256;       // 0..1023
                const int row = id >> 3;             // 0..127
                const int seg = id & 7;              // 16B segment
                const uint32_t so = row * (ASTR * 2) + seg * 16;
                const size_t   go = (size_t)row * Ke + kof + seg * 8;
                cp16(sa[b] + so, A + go);
                cp16(sb[b] + so, B + go);
            }
            CP_COMMIT();
        };

        float acc[4][4][4];
        #pragma unroll
        for (int i = 0; i < 4; ++i)
            #pragma unroll
            for (int j = 0; j < 4; ++j)
                #pragma unroll
                for (int k = 0; k < 4; ++k) acc[i][j][k] = 0.f;

        stage(0, 0);
        stage(1, 1);

        for (int t = 0; t < nch; ++t) {
            const int b = t % 3;
            if (t + 1 < nch) CP_WAIT1(); else CP_WAIT0();
            __syncthreads();
            if (t + 2 < nch) stage(t + 2, (t + 2) % 3);

            #pragma unroll
            for (int ks = 0; ks < 4; ++ks) {             // four k16 steps
                uint32_t bfr[2][4];
                #pragma unroll
                for (int h = 0; h < 2; ++h) {
                    const uint32_t addr = sb[b] +
                        (uint32_t)(((n0w + h * 16 + brow) * ASTR +
                                    ks * 16 + bkh) * 2);
                    ldsm4(bfr[h], addr);
                }
                #pragma unroll
                for (int mf = 0; mf < 4; ++mf) {
                    uint32_t afr[4];
                    const uint32_t addr = sa[b] +
                        (uint32_t)(((m0w + mf * 16 + arow) * ASTR +
                                    ks * 16 + akh) * 2);
                    ldsm4(afr, addr);
                    mma16816(acc[mf][0], afr, &bfr[0][0]);
                    mma16816(acc[mf][1], afr, &bfr[0][2]);
                    mma16816(acc[mf][2], afr, &bfr[1][0]);
                    mma16816(acc[mf][3], afr, &bfr[1][2]);
                }
            }
        }
        __syncthreads();   // all compute done before next tile restages smem

        if (!QKV) {
            float* C = Cf + (long long)bz * sC;
            #pragma unroll
            for (int mf = 0; mf < 4; ++mf) {
                const int gr = by * 128 + m0w + mf * 16 + rr;
                #pragma unroll
                for (int nf = 0; nf < 4; ++nf) {
                    const int gc = bx * 128 + n0w + nf * 8 + cc2;
                    float* p = C + (size_t)gr * N + gc;
                    *(float2*)p = make_float2(acc[mf][nf][0], acc[mf][nf][1]);
                    *(float2*)(p + (size_t)8 * N) =
                        make_float2(acc[mf][nf][2], acc[mf][nf][3]);
                }
            }
        } else {
            // N == 1024. z=0: qe [M,3072] cols [hi|lo|hi];
            // z=1: ke [M,3072] cols [hi|hi|lo];
            // z=2: ve rows [Vhi;Vhi;Vlo] per batch: [6144,1024].
            #pragma unroll
            for (int mf = 0; mf < 4; ++mf) {
                #pragma unroll
                for (int h = 0; h < 2; ++h) {
                    const int gr = by * 128 + m0w + mf * 16 + rr + h * 8;
                    #pragma unroll
                    for (int nf = 0; nf < 4; ++nf) {
                        const int gc = bx * 128 + n0w + nf * 8 + cc2;
                        uint32_t hip, lop;
                        split2(acc[mf][nf][2 * h], acc[mf][nf][2 * h + 1],
                               hip, lop);
                        if (bz == 0) {
                            __nv_bfloat16* dr = dq + (size_t)gr * 3072 + gc;
                            *(uint32_t*)(dr)        = hip;
                            *(uint32_t*)(dr + 1024) = lop;
                            *(uint32_t*)(dr + 2048) = hip;
                        } else if (bz == 1) {
                            __nv_bfloat16* dr = dk + (size_t)gr * 3072 + gc;
                            *(uint32_t*)(dr)        = hip;
                            *(uint32_t*)(dr + 1024) = hip;
                            *(uint32_t*)(dr + 2048) = lop;
                        } else {
                            const size_t bse =
                                (size_t)(gr >> 11) * 6144 + (gr & 2047);
                            __nv_bfloat16* dr = dv + bse * 1024 + gc;
                            *(uint32_t*)(dr)                       = hip;
                            *(uint32_t*)(dr + (size_t)2048 * 1024) = hip;
                            *(uint32_t*)(dr + (size_t)4096 * 1024) = lop;
                        }
                    }
                }
            }
        }
    }
}

// ---------------------------------------------------------------------------
// NN GEMM: C[M,N] = A[M,Ke] @ B[Ke,N], A bf16 K-major, B bf16 N-major rows.
// Same persistent 3-stage structure; B fragments via ldmatrix.trans from a
// 272B-padded [64,128] tile.
// ---------------------------------------------------------------------------
__global__ __launch_bounds__(256, 2)
void gemm_nn(const __nv_bfloat16* __restrict__ Ag,
             const __nv_bfloat16* __restrict__ Bg,
             float* __restrict__ Cg,
             int N, long long Ke, long long sA, long long sB, long long sC,
             int ntx, int nty, int ntotal)
{
    extern __shared__ __align__(16) char dsm[];
    const uint32_t base = smem_u32(dsm);
    uint32_t sa[3], sb[3];
    #pragma unroll
    for (int i = 0; i < 3; ++i) {
        sa[i] = base + i * ATILEB;
        sb[i] = base + 3 * ATILEB + i * BTILEB_NN;
    }

    const int tid  = threadIdx.x;
    const int lane = tid & 31;
    const int wid  = tid >> 5;
    const int m0w  = (wid >> 2) * 64;
    const int n0w  = (wid & 3) * 32;

    const int arow  = lane & 15;
    const int akh   = (lane >> 4) * 8;
    const int bkrow = ((lane >> 3) & 1) * 8 + (lane & 7);
    const int bncol = (lane >> 4) << 3;
    const int rr    = lane >> 2;
    const int cc2   = (lane & 3) * 2;

    const int nch = (int)(Ke / KCH);

    for (int tile = blockIdx.x; tile < ntotal; tile += gridDim.x) {
        const int bx = tile % ntx;
        const int t2 = tile / ntx;
        const int by = t2 % nty;
        const int bz = t2 / nty;

        const __nv_bfloat16* A =
            Ag + (long long)bz * sA + (size_t)by * 128 * Ke;
        const __nv_bfloat16* B =
            Bg + (long long)bz * sB + (size_t)bx * 128;
        float* C = Cg + (long long)bz * sC;

        auto stage = [&](int ck, int b) {
            const size_t kof = (size_t)ck * KCH;
            #pragma unroll
            for (int i = 0; i < 4; ++i) {           // A: 128 rows x 8 segs
                const int id  = tid + i * 256;
                const int row = id >> 3;
                const int seg = id & 7;
                cp16(sa[b] + row * (ASTR * 2) + seg * 16,
                     A + (size_t)row * Ke + kof + seg * 8);
            }
            #pragma unroll
            for (int i = 0; i < 4; ++i) {           // B: 64 k-rows x 16 segs
                const int id  = tid + i * 256;
                const int row = id >> 4;
                const int seg = id & 15;
                cp16(sb[b] + row * (BSTRNN * 2) + seg * 16,
                     B + (size_t)(kof + row) * N + seg * 8);
            }
            CP_COMMIT();
        };

        float acc[4][4][4];
        #pragma unroll
        for (int i = 0; i < 4; ++i)
            #pragma unroll
            for (int j = 0; j < 4; ++j)
                #pragma unroll
                for (int k = 0; k < 4; ++k) acc[i][j][k] = 0.f;

        stage(0, 0);
        stage(1, 1);

        for (int t = 0; t < nch; ++t) {
            const int b = t % 3;
            if (t + 1 < nch) CP_WAIT1(); else CP_WAIT0();
            __syncthreads();
            if (t + 2 < nch) stage(t + 2, (t + 2) % 3);

            #pragma unroll
            for (int ks = 0; ks < 4; ++ks) {
                uint32_t bfr[2][4];
                #pragma unroll
                for (int h = 0; h < 2; ++h) {
                    const uint32_t addr = sb[b] +
                        (uint32_t)(((ks * 16 + bkrow) * BSTRNN +
                                    n0w + h * 16 + bncol) * 2);
                    ldsm4t(bfr[h], addr);
                }
                #pragma unroll
                for (int mf = 0; mf < 4; ++mf) {
                    uint32_t afr[4];
                    const uint32_t addr = sa[b] +
                        (uint32_t)(((m0w + mf * 16 + arow) * ASTR +
                                    ks * 16 + akh) * 2);
                    ldsm4(afr, addr);
                    mma16816(acc[mf][0], afr, &bfr[0][0]);
                    mma16816(acc[mf][1], afr, &bfr[0][2]);
                    mma16816(acc[mf][2], afr, &bfr[1][0]);
                    mma16816(acc[mf][3], afr, &bfr[1][2]);
                }
            }
        }
        __syncthreads();

        #pragma unroll
        for (int mf = 0; mf < 4; ++mf) {
            const int gr = by * 128 + m0w + mf * 16 + rr;
            #pragma unroll
            for (int nf = 0; nf < 4; ++nf) {
                const int gc = bx * 128 + n0w + nf * 8 + cc2;
                float* p = C + (size_t)gr * N + gc;
                *(float2*)p = make_float2(acc[mf][nf][0], acc[mf][nf][1]);
                *(float2*)(p + (size_t)8 * N) =
                    make_float2(acc[mf][nf][2], acc[mf][nf][3]);
            }
        }
    }
}

// ---------------------------------------------------------------------------
// split_cols: src fp32 [R,Cc] -> dst bf16 [R,3Cc]; block lo_blk gets lo.
// (Used only for X: lo_blk=1 -> [hi,lo,hi].)
// ---------------------------------------------------------------------------
__global__ void split_cols(const float* __restrict__ src,
                           __nv_bfloat16* __restrict__ dst,
                           long long Cc, int lo_blk, long long nvec)
{
    union B4 { __nv_bfloat16 b[4]; uint2 u; };
    for (long long i = blockIdx.x * (long long)blockDim.x + threadIdx.x;
         i < nvec; i += (long long)gridDim.x * blockDim.x) {
        const long long e = i * 4;
        const long long r = e / Cc;
        const long long c = e - r * Cc;
        const float4 x = *(const float4*)(src + e);
        B4 h, l;
        h.b[0] = __float2bfloat16_rn(x.x);
        l.b[0] = __float2bfloat16_rn(x.x - __bfloat162float(h.b[0]));
        h.b[1] = __float2bfloat16_rn(x.y);
        l.b[1] = __float2bfloat16_rn(x.y - __bfloat162float(h.b[1]));
        h.b[2] = __float2bfloat16_rn(x.z);
        l.b[2] = __float2bfloat16_rn(x.z - __bfloat162float(h.b[2]));
        h.b[3] = __float2bfloat16_rn(x.w);
        l.b[3] = __float2bfloat16_rn(x.w - __bfloat162float(h.b[3]));
        __nv_bfloat16* dr = dst + r * 3 * Cc + c;
        *(uint2*)(dr)          = (lo_blk == 0) ? l.u : h.u;
        *(uint2*)(dr + Cc)     = (lo_blk == 1) ? l.u : h.u;
        *(uint2*)(dr + 2 * Cc) = (lo_blk == 2) ? l.u : h.u;
    }
}

// ---------------------------------------------------------------------------
// split_transpose: src fp32 [R,Cc] -> dst bf16 [Cc,3R]; lo_blk=2 -> [hi,hi,lo].
// (Used only for the three weight matrices.)
// ---------------------------------------------------------------------------
__global__ void split_transpose(const float* __restrict__ src,
                                __nv_bfloat16* __restrict__ dst,
                                int R, int Cc, long long sSrc, long long sDst,
                                int lo_blk)
{
    __shared__ float tile[32][33];
    src += (long long)blockIdx.z * sSrc;
    dst += (long long)blockIdx.z * sDst;
    const int r0 = blockIdx.y * 32, c0 = blockIdx.x * 32;
    const int tx = threadIdx.x, ty = threadIdx.y;

    #pragma unroll
    for (int j = 0; j < 4; ++j) {
        const int r = ty + j * 8;
        tile[r][tx] = src[(size_t)(r0 + r) * Cc + c0 + tx];
    }
    __syncthreads();

    const long long R3 = 3LL * R;
    #pragma unroll
    for (int j = 0; j < 4; ++j) {
        const int c = ty + j * 8;
        const float x = tile[tx][c];
        const __nv_bfloat16 h = __float2bfloat16_rn(x);
        const __nv_bfloat16 l = __float2bfloat16_rn(x - __bfloat162float(h));
        __nv_bfloat16* dr = dst + (size_t)(c0 + c) * R3 + r0 + tx;
        dr[0]             = (lo_blk == 0) ? l : h;
        dr[(size_t)R]     = (lo_blk == 1) ? l : h;
        dr[(size_t)2 * R] = (lo_blk == 2) ? l : h;
    }
}

// ---------------------------------------------------------------------------
// Fused softmax + P-ext: reads one score row (2048 fp32), writes the pe row
// [hi|lo|hi] (6144 bf16). One 256-thread block per row.
// ---------------------------------------------------------------------------
__global__ void softmax_pe(const float* __restrict__ S,
                           __nv_bfloat16* __restrict__ P)
{
    __shared__ float red[256];
    const float* p = S + (size_t)blockIdx.x * SSQ;
    __nv_bfloat16* o = P + (size_t)blockIdx.x * 6144;
    const int tid = threadIdx.x;

    float v[4][2];
    float lmax = -3.402823466e38f;
    #pragma unroll
    for (int j = 0; j < 4; ++j) {
        const float2 x = *(const float2*)(p + 2 * tid + j * 512);
        v[j][0] = x.x; v[j][1] = x.y;
        lmax = fmaxf(lmax, fmaxf(x.x, x.y));
    }
    red[tid] = lmax; __syncthreads();
    #pragma unroll
    for (int s = 128; s > 0; s >>= 1) {
        if (tid < s) red[tid] = fmaxf(red[tid], red[tid + s]);
        __syncthreads();
    }
    const float m = red[0];
    __syncthreads();

    float lsum = 0.f;
    #pragma unroll
    for (int j = 0; j < 4; ++j) {
        v[j][0] = __expf(v[j][0] - m);
        v[j][1] = __expf(v[j][1] - m);
        lsum += v[j][0] + v[j][1];
    }
    red[tid] = lsum; __syncthreads();
    #pragma unroll
    for (int s = 128; s > 0; s >>= 1) {
        if (tid < s) red[tid] += red[tid + s];
        __syncthreads();
    }
    const float inv = 1.0f / red[0];

    #pragma unroll
    for (int j = 0; j < 4; ++j) {
        const int c = 2 * tid + j * 512;
        uint32_t hip, lop;
        split2(v[j][0] * inv, v[j][1] * inv, hip, lop);
        *(uint32_t*)(o + c)        = hip;   // block 0: hi
        *(uint32_t*)(o + 2048 + c) = lop;   // block 1: lo
        *(uint32_t*)(o + 4096 + c) = hip;   // block 2: hi
    }
}

// ---------------------------------------------------------------------------
// Launch graph: split(X), split_transpose(W) -> QKV GEMM (ext epilogues) ->
// scores GEMM -> fused softmax+split -> NN PV GEMM. Capturable; no allocs.
// ---------------------------------------------------------------------------
extern "C" void kernel_launch(void* const* d_in, const int* in_sizes, int n_in,
                              void* d_out, int out_size)
{
    const float* X  = (const float*)d_in[0];   // [B,S,D] = [8192,1024]
    const float* Wq = (const float*)d_in[1];   // [D,U]
    const float* Wk = (const float*)d_in[2];
    const float* Wv = (const float*)d_in[3];
    float* out = (float*)d_out;                // [B,S,U]

    __nv_bfloat16 *xe, *we, *qe, *ke, *ve, *pe;
    float *sp;
    cudaGetSymbolAddress((void**)&xe, g_xe);
    cudaGetSymbolAddress((void**)&we, g_we);
    cudaGetSymbolAddress((void**)&qe, g_qe);
    cudaGetSymbolAddress((void**)&ke, g_ke);
    cudaGetSymbolAddress((void**)&ve, g_ve);
    cudaGetSymbolAddress((void**)&sp, g_s);
    cudaGetSymbolAddress((void**)&pe, g_pe);

    // Opt in to >48KB dynamic smem (host-side attribute set; capture-safe).
    static bool attr_done = false;
    if (!attr_done) {
        cudaFuncSetAttribute(gemm_nt<true>,
            cudaFuncAttributeMaxDynamicSharedMemorySize, NT_SMEM);
        cudaFuncSetAttribute(gemm_nt<false>,
            cudaFuncAttributeMaxDynamicSharedMemorySize, NT_SMEM);
        cudaFuncSetAttribute(gemm_nn,
            cudaFuncAttributeMaxDynamicSharedMemorySize, NN_SMEM);
        attr_done = true;
    }

    const long long KE1 = 3LL * DD;    // 3072
    const long long KE2 = 3LL * SSQ;   // 6144
    const dim3 blk(256);

    // 1) X ext (A-side) and W^T ext (B-side, transposed).
    split_cols<<<2048, 256>>>(X, xe, DD, 1, (long long)8192 * DD / 4);
    {
        dim3 g(UU / 32, DD / 32, 1), b(32, 8);
        split_transpose<<<g, b>>>(Wq, we,                        DD, UU, 0, 0, 2);
        split_transpose<<<g, b>>>(Wk, we + (size_t)UU * KE1,     DD, UU, 0, 0, 2);
        split_transpose<<<g, b>>>(Wv, we + (size_t)2 * UU * KE1, DD, UU, 0, 0, 2);
    }

    // 2) Fused QKV with ext epilogues (persistent tiles: 8 x 64 x 3 = 1536).
    gemm_nt<true><<<NUM_PERS, blk, NT_SMEM>>>(
        xe, we, nullptr, qe, ke, ve, UU, KE1, 0, (long long)UU * KE1, 0,
        UU / 128, 8192 / 128, 1536);

    // 3) scores[b] = Qe[b] @ Ke[b]^T (tiles: 16 x 16 x 4 = 1024).
    gemm_nt<false><<<NUM_PERS, blk, NT_SMEM>>>(
        qe, ke, sp, nullptr, nullptr, nullptr, SSQ, KE1,
        (long long)SSQ * KE1, (long long)SSQ * KE1, (long long)SSQ * SSQ,
        SSQ / 128, SSQ / 128, 1024);

    // 4) Softmax + P ext (A-side) in one pass.
    softmax_pe<<<BB * SSQ, 256>>>(sp, pe);

    // 5) out[b] = Pe[b] @ Ve[b] (NN; tiles: 8 x 16 x 4 = 512).
    gemm_nn<<<NUM_PERS, blk, NN_SMEM>>>(
        pe, ve, out, UU, KE2,
        (long long)SSQ * KE2, (long long)KE2 * UU, (long long)SSQ * UU,
        UU / 128, SSQ / 128, 512);
}